// round 3
// baseline (speedup 1.0000x reference)
#include <cuda_runtime.h>
#include <math.h>

// Segment sums, zero-initialized at module load; the last block re-zeroes them
// after each run so graph replays are deterministic. Sized for B up to 8192.
__device__ float g_pos_sum[8192];
__device__ float g_neg_sum[8192];
__device__ unsigned int g_done_ctr;   // zero-init; reset by last block

// ---------------------------------------------------------------------------
// Single fused kernel.
//   Phase 1: one warp per row -> exp(cosine) -> atomicAdd into segment sums.
//   Phase 2: last block to finish reads the B segment-sum pairs, computes the
//            per-item losses, reduces, writes out[0], and resets scratch.
// ---------------------------------------------------------------------------
__global__ void __launch_bounds__(1024) contrastive_fused_kernel(
    const float* __restrict__ q_pos, const float* __restrict__ i_pos,
    const float* __restrict__ q_neg, const float* __restrict__ i_neg,
    float* __restrict__ out, int pos_rows, int total_rows, int n_items)
{
    const int w = (blockIdx.x * blockDim.x + threadIdx.x) >> 5;
    const int lane = threadIdx.x & 31;

    // ---- Phase 1: row cosine (predicated; everyone reaches the barrier) ----
    if (w < total_rows) {
        const float4* __restrict__ a4;
        const float4* __restrict__ b4;
        float* __restrict__ dst;
        if (w < pos_rows) {
            a4 = reinterpret_cast<const float4*>(q_pos) + (size_t)w * 256;
            b4 = reinterpret_cast<const float4*>(i_pos) + (size_t)w * 256;
            dst = &g_pos_sum[w >> 1];                  // 2 pos rows per item
        } else {
            const int r = w - pos_rows;
            a4 = reinterpret_cast<const float4*>(q_neg) + (size_t)r * 256;
            b4 = reinterpret_cast<const float4*>(i_neg) + (size_t)r * 256;
            dst = &g_neg_sum[r / 23];                  // 23 neg rows per item
        }

        float dot = 0.0f, na2 = 0.0f, nb2 = 0.0f;
#pragma unroll
        for (int i = 0; i < 8; i++) {
            float4 va = __ldcs(a4 + lane + i * 32);    // streaming: evict-first
            float4 vb = __ldcs(b4 + lane + i * 32);
            dot = fmaf(va.x, vb.x, dot); na2 = fmaf(va.x, va.x, na2); nb2 = fmaf(vb.x, vb.x, nb2);
            dot = fmaf(va.y, vb.y, dot); na2 = fmaf(va.y, va.y, na2); nb2 = fmaf(vb.y, vb.y, nb2);
            dot = fmaf(va.z, vb.z, dot); na2 = fmaf(va.z, va.z, na2); nb2 = fmaf(vb.z, vb.z, nb2);
            dot = fmaf(va.w, vb.w, dot); na2 = fmaf(va.w, va.w, na2); nb2 = fmaf(vb.w, vb.w, nb2);
        }
#pragma unroll
        for (int off = 16; off > 0; off >>= 1) {
            dot += __shfl_xor_sync(0xffffffffu, dot, off);
            na2 += __shfl_xor_sync(0xffffffffu, na2, off);
            nb2 += __shfl_xor_sync(0xffffffffu, nb2, off);
        }
        if (lane == 0) {
            float denom = fmaxf(sqrtf(na2) * sqrtf(nb2), 1e-8f);
            atomicAdd(dst, expf(dot / denom));
        }
    }

    // ---- Completion handshake ----
    __syncthreads();
    __shared__ bool s_last;
    if (threadIdx.x == 0) {
        __threadfence();   // order our atomics before the counter bump
        unsigned int prev = atomicAdd(&g_done_ctr, 1u);
        s_last = (prev == gridDim.x - 1);
    }
    __syncthreads();
    if (!s_last) return;

    // ---- Phase 2: finalize in the last block (1024 threads) ----
    __threadfence();       // acquire: see all blocks' atomics
    __shared__ float red[32];
    float acc = 0.0f;
    for (int i = threadIdx.x; i < n_items; i += 1024) {
        float p = __ldcg(&g_pos_sum[i]);
        float n = __ldcg(&g_neg_sum[i]);
        acc += (n - p) / (p + n + 0.001f);
        g_pos_sum[i] = 0.0f;   // restore scratch for next replay
        g_neg_sum[i] = 0.0f;
    }
#pragma unroll
    for (int off = 16; off > 0; off >>= 1)
        acc += __shfl_xor_sync(0xffffffffu, acc, off);
    if ((threadIdx.x & 31) == 0) red[threadIdx.x >> 5] = acc;
    __syncthreads();
    if (threadIdx.x < 32) {
        float v = red[threadIdx.x];
#pragma unroll
        for (int off = 16; off > 0; off >>= 1)
            v += __shfl_xor_sync(0xffffffffu, v, off);
        if (threadIdx.x == 0) {
            out[0] = v;
            g_done_ctr = 0;    // reset for next replay
        }
    }
}

// ---------------------------------------------------------------------------
// Inputs (metadata order):
//   0: question_embeddings_pos  [2B, 1024] f32
//   1: question_embeddings_neg  [23B, 1024] f32
//   2: pos_image_embeddings     [2B, 1024] f32
//   3: neg_image_embeddings     [23B, 1024] f32
//   4: batch_size (int scalar)
// Output: f32 scalar.
// ---------------------------------------------------------------------------
extern "C" void kernel_launch(void* const* d_in, const int* in_sizes, int n_in,
                              void* d_out, int out_size) {
    const float* q_pos = (const float*)d_in[0];
    const float* q_neg = (const float*)d_in[1];
    const float* i_pos = (const float*)d_in[2];
    const float* i_neg = (const float*)d_in[3];
    float* out = (float*)d_out;

    const int D = 1024;
    const int B = in_sizes[0] / (2 * D);
    const int pos_rows = 2 * B;
    const int total_rows = 25 * B;

    const int WPB = 32;  // 1024 threads / block
    const int blocks = (total_rows + WPB - 1) / WPB;
    contrastive_fused_kernel<<<blocks, WPB * 32>>>(
        q_pos, i_pos, q_neg, i_neg, out, pos_rows, total_rows, B);
}